// round 15
// baseline (speedup 1.0000x reference)
#include <cuda_runtime.h>
#include <cuda_fp16.h>

#define NN      160000
#define HH      64
#define EE      3200000
#define NGENES  5000
#define TILE    64
#define ASTR    68          // act row stride in floats (16B-aligned rows)

typedef unsigned long long ull;

// -------- scratch (static device globals; no runtime allocation) --------
__device__ int     g_flag;
__device__ int     g_cnt[NN];
__device__ int     g_cur[NN];
__device__ int     g_off[NN + 1];
__device__ int     g_srcl[EE];
__device__ float   g_dinv[NN];
__device__ __half2 g_hA[NN * 32];    // scaled h0@Wc1 (fp16 rows, 128B each)
__device__ __half2 g_hB[NN * 32];    // scaled h1@Wc2 (fp16 rows)
// precompute scratch
__device__ float g_Wtc[64 * 64];     // WpbT @ Wc1
__device__ float g_Wtot[64 * 64];    // WetB @ Wtc
__device__ float g_E3[NGENES * 64];  // renorm(Emb) @ Wtot
__device__ float g_P[64], g_Q[64], g_R[64];

// ---------------- f32x2 packed-FMA helpers (lower to HW FFMA2) ----------
#define FFMA2(c, a, b) asm("fma.rn.f32x2 %0, %1, %2, %0;" : "+l"(c) : "l"(a), "l"(b))
#define DUP2(d, s) asm("mov.b64 %0, {%1, %2};" : "=l"(d) \
                       : "r"(__float_as_uint(s)), "r"(__float_as_uint(s)))
__device__ __forceinline__ void unpack2(float& lo, float& hi, ull s) {
    unsigned int ulo, uhi;
    asm("mov.b64 {%0, %1}, %2;" : "=r"(ulo), "=r"(uhi) : "l"(s));
    lo = __uint_as_float(ulo); hi = __uint_as_float(uhi);
}

// ---------------------------------------------------------------------
__global__ void k_zero_detect(const int* __restrict__ ei32, int E, int n) {
    int t = blockIdx.x * blockDim.x + threadIdx.x;
    if (t < n) { g_cnt[t] = 0; g_cur[t] = 0; }
    if (t < 16384) {
        int acc = 0;
        const long long total = 2LL * E;
        const long long stride = total / 65536;
        #pragma unroll
        for (int q = 0; q < 4; q++) {
            long long widx = ((long long)(t * 4 + q) * stride) | 1LL;
            if (widx < total) acc |= ei32[widx];
        }
        #pragma unroll
        for (int o = 16; o; o >>= 1) acc |= __shfl_xor_sync(0xffffffffu, acc, o);
        if ((threadIdx.x & 31) == 0 && acc) atomicOr(&g_flag, 1);
    }
}

__device__ __forceinline__ int ld_src(const int* __restrict__ ei32, int E, int e, bool is64) {
    int v = is64 ? ei32[2 * e] : ei32[e];
    return min(max(v, 0), NN - 1);
}
__device__ __forceinline__ int ld_dst(const int* __restrict__ ei32, int E, int e, bool is64) {
    int v = is64 ? ei32[2 * (E + e)] : ei32[E + e];
    return min(max(v, 0), NN - 1);
}

__global__ void k_deg(const int* __restrict__ ei32, int E) {
    int e = blockIdx.x * blockDim.x + threadIdx.x;
    bool is64 = (g_flag == 0);
    if (e < E) atomicAdd(&g_cnt[ld_dst(ei32, E, e, is64)], 1);
}

__global__ void k_dinv(int n) {
    int i = blockIdx.x * blockDim.x + threadIdx.x;
    if (i < n) g_dinv[i] = rsqrtf(1.0f + (float)g_cnt[i]);
}

__global__ void k_scan() {
    __shared__ int ssum[1024];
    const int T = 1024;
    const int per = (NN + T - 1) / T;
    int tid = threadIdx.x;
    int a = tid * per;
    int b = a + per; if (b > NN) b = NN;
    int s = 0;
    for (int i = a; i < b; i++) s += g_cnt[i];
    ssum[tid] = s;
    __syncthreads();
    for (int o = 1; o < T; o <<= 1) {
        int v = (tid >= o) ? ssum[tid - o] : 0;
        __syncthreads();
        ssum[tid] += v;
        __syncthreads();
    }
    int run = (tid == 0) ? 0 : ssum[tid - 1];
    for (int i = a; i < b; i++) { g_off[i] = run; run += g_cnt[i]; }
    if (tid == T - 1) g_off[NN] = run;
}

__global__ void k_fill(const int* __restrict__ ei32, int E) {
    int e = blockIdx.x * blockDim.x + threadIdx.x;
    bool is64 = (g_flag == 0);
    if (e < E) {
        int s = ld_src(ei32, E, e, is64);
        int d = ld_dst(ei32, E, e, is64);
        g_srcl[g_off[d] + atomicAdd(&g_cur[d], 1)] = s;
    }
}

// ---------------------------------------------------------------------
__global__ void k_pre1a(const float* __restrict__ Wpb, const float* __restrict__ Wc1) {
    const int r = blockIdx.x, j = threadIdx.x;
    if (r == 0 && j == 0) g_flag = 0;
    float s = 0.f;
    #pragma unroll 4
    for (int k = 0; k < 64; k++) s = fmaf(__ldg(&Wpb[r * 64 + k]), __ldg(&Wc1[k * 64 + j]), s);
    g_Wtc[r * 64 + j] = s;
}

__global__ void k_pre1b(const float* __restrict__ Wp, const float* __restrict__ bp,
                        const float* __restrict__ Wg, const float* __restrict__ bg,
                        const float* __restrict__ Wet, const float* __restrict__ bet,
                        const float* __restrict__ Wpb, const float* __restrict__ bpb,
                        const float* __restrict__ Wc1) {
    const int j = threadIdx.x;
    if (blockIdx.x < 64) {
        const int r = blockIdx.x;
        float s = 0.f;
        #pragma unroll 4
        for (int k = 0; k < 64; k++) s = fmaf(__ldg(&Wet[(64 + r) * 64 + k]), g_Wtc[k * 64 + j], s);
        g_Wtot[r * 64 + j] = s;
        return;
    }
    __shared__ float sv[64];
    float u = 0.f;
    for (int k = 0; k < 64; k++) u = fmaf(Wg[k], Wet[k * 64 + j], u);
    sv[j] = u;
    __syncthreads();
    float p = 0.f;
    for (int k = 0; k < 64; k++) p = fmaf(sv[k], g_Wtc[k * 64 + j], p);
    g_P[j] = p;
    __syncthreads();
    float v = 0.f;
    for (int k = 0; k < 64; k++) v = fmaf(Wp[k], Wpb[(64 + k) * 64 + j], v);
    sv[j] = v;
    __syncthreads();
    float qq = 0.f;
    for (int k = 0; k < 64; k++) qq = fmaf(sv[k], Wc1[k * 64 + j], qq);
    g_Q[j] = qq;
    __syncthreads();
    float r1 = bet[j];
    for (int k = 0; k < 64; k++) r1 = fmaf(bg[k], Wet[k * 64 + j], r1);
    sv[j] = r1;
    __syncthreads();
    float r2 = bpb[j];
    for (int k = 0; k < 64; k++) r2 = fmaf(sv[k], Wpb[k * 64 + j], r2);
    for (int k = 0; k < 64; k++) r2 = fmaf(bp[k], Wpb[(64 + k) * 64 + j], r2);
    __syncthreads();
    sv[j] = r2;
    __syncthreads();
    float rr = 0.f;
    for (int k = 0; k < 64; k++) rr = fmaf(sv[k], Wc1[k * 64 + j], rr);
    g_R[j] = rr;
}

__global__ void __launch_bounds__(256) k_pre2(const float* __restrict__ Emb) {
    __shared__ float se[4][64];
    __shared__ float ssc[4];
    __shared__ float sp[4][2];
    const int t = threadIdx.x;
    const int gl = t >> 6, j = t & 63;
    const int g = blockIdx.x * 4 + gl;
    if (g >= NGENES) return;

    float e = Emb[g * 64 + j];
    se[gl][j] = e;
    float ss = e * e;
    #pragma unroll
    for (int o = 16; o; o >>= 1) ss += __shfl_xor_sync(0xffffffffu, ss, o);
    if ((j & 31) == 0) sp[gl][j >> 5] = ss;
    __syncthreads();
    if (j == 0) {
        float nrm = sqrtf(sp[gl][0] + sp[gl][1]);
        ssc[gl] = fminf(1.0f, 1.0f / fmaxf(nrm, 1e-12f));
    }
    __syncthreads();

    float acc = 0.f;
    #pragma unroll 4
    for (int k = 0; k < 64; k++) acc = fmaf(se[gl][k], g_Wtot[k * 64 + j], acc);
    g_E3[g * 64 + j] = acc * ssc[gl];
}

// node: hA[i] = (E3[gid] + basal*P + pert*Q + R) * dinv[i]  (fp16 rows)
__global__ void __launch_bounds__(256) k_node(const float* __restrict__ x) {
    const int lane = threadIdx.x & 31;
    const int i = blockIdx.x * 8 + (threadIdx.x >> 5);
    const float basal = __ldg(&x[2 * i]);
    const float pert  = __ldg(&x[2 * i + 1]);
    const int gid = i % NGENES;
    const float di = g_dinv[i];
    float2 e3 = ((const float2*)(g_E3 + gid * 64))[lane];
    float2 P  = ((const float2*)g_P)[lane];
    float2 Q  = ((const float2*)g_Q)[lane];
    float2 R  = ((const float2*)g_R)[lane];
    float w0 = (e3.x + basal * P.x + pert * Q.x + R.x) * di;
    float w1 = (e3.y + basal * P.y + pert * Q.y + R.y) * di;
    g_hA[(size_t)i * 32 + lane] = __floats2half2_rn(w0, w1);
}

// ---------------------------------------------------------------------
// gather: warp-per-node, 8 nodes serially per warp (TILE=64).  fp16 rows:
// lane l loads half2 (cols 2l,2l+1) -> one 128B line per edge-row.
// Accumulate in fp32; 8-deep load batches (MLP 8, proven shape).
__device__ __forceinline__ void gather_tile(const __half2* __restrict__ rows,
                                            const float* __restrict__ bias,
                                            bool relu, int i0,
                                            float* __restrict__ act) {
    const int lane = threadIdx.x & 31;
    const int w    = threadIdx.x >> 5;       // 0..7
    const float2 bj = *(const float2*)&bias[2 * lane];

    for (int r = 0; r < 8; r++) {
        const int n = w * 8 + r;
        const int i = i0 + n;
        const int o0 = g_off[i];
        const int D  = g_off[i + 1] - o0;

        float2 a0 = __half22float2(rows[(size_t)i * 32 + lane]);  // own row
        float2 a1 = make_float2(0.f, 0.f);
        float2 a2 = make_float2(0.f, 0.f);
        float2 a3 = make_float2(0.f, 0.f);

        int base = o0;
        const int nfull = D >> 5;
        for (int c = 0; c < nfull; c++) {
            int idx = g_srcl[base + lane];
            base += 32;
            #pragma unroll
            for (int h = 0; h < 4; h++) {
                int s0 = __shfl_sync(0xffffffffu, idx, h * 8 + 0);
                int s1 = __shfl_sync(0xffffffffu, idx, h * 8 + 1);
                int s2 = __shfl_sync(0xffffffffu, idx, h * 8 + 2);
                int s3 = __shfl_sync(0xffffffffu, idx, h * 8 + 3);
                int s4 = __shfl_sync(0xffffffffu, idx, h * 8 + 4);
                int s5 = __shfl_sync(0xffffffffu, idx, h * 8 + 5);
                int s6 = __shfl_sync(0xffffffffu, idx, h * 8 + 6);
                int s7 = __shfl_sync(0xffffffffu, idx, h * 8 + 7);
                __half2 v0 = rows[(size_t)s0 * 32 + lane];
                __half2 v1 = rows[(size_t)s1 * 32 + lane];
                __half2 v2 = rows[(size_t)s2 * 32 + lane];
                __half2 v3 = rows[(size_t)s3 * 32 + lane];
                __half2 v4 = rows[(size_t)s4 * 32 + lane];
                __half2 v5 = rows[(size_t)s5 * 32 + lane];
                __half2 v6 = rows[(size_t)s6 * 32 + lane];
                __half2 v7 = rows[(size_t)s7 * 32 + lane];
                float2 f;
                f = __half22float2(v0); a0.x += f.x; a0.y += f.y;
                f = __half22float2(v1); a1.x += f.x; a1.y += f.y;
                f = __half22float2(v2); a2.x += f.x; a2.y += f.y;
                f = __half22float2(v3); a3.x += f.x; a3.y += f.y;
                f = __half22float2(v4); a0.x += f.x; a0.y += f.y;
                f = __half22float2(v5); a1.x += f.x; a1.y += f.y;
                f = __half22float2(v6); a2.x += f.x; a2.y += f.y;
                f = __half22float2(v7); a3.x += f.x; a3.y += f.y;
            }
        }
        const int rem = D & 31;
        if (rem) {
            int idx = (lane < rem) ? g_srcl[base + lane] : 0;
            int e = 0;
            for (; e + 7 < rem; e += 8) {
                int s0 = __shfl_sync(0xffffffffu, idx, e);
                int s1 = __shfl_sync(0xffffffffu, idx, e + 1);
                int s2 = __shfl_sync(0xffffffffu, idx, e + 2);
                int s3 = __shfl_sync(0xffffffffu, idx, e + 3);
                int s4 = __shfl_sync(0xffffffffu, idx, e + 4);
                int s5 = __shfl_sync(0xffffffffu, idx, e + 5);
                int s6 = __shfl_sync(0xffffffffu, idx, e + 6);
                int s7 = __shfl_sync(0xffffffffu, idx, e + 7);
                __half2 v0 = rows[(size_t)s0 * 32 + lane];
                __half2 v1 = rows[(size_t)s1 * 32 + lane];
                __half2 v2 = rows[(size_t)s2 * 32 + lane];
                __half2 v3 = rows[(size_t)s3 * 32 + lane];
                __half2 v4 = rows[(size_t)s4 * 32 + lane];
                __half2 v5 = rows[(size_t)s5 * 32 + lane];
                __half2 v6 = rows[(size_t)s6 * 32 + lane];
                __half2 v7 = rows[(size_t)s7 * 32 + lane];
                float2 f;
                f = __half22float2(v0); a0.x += f.x; a0.y += f.y;
                f = __half22float2(v1); a1.x += f.x; a1.y += f.y;
                f = __half22float2(v2); a2.x += f.x; a2.y += f.y;
                f = __half22float2(v3); a3.x += f.x; a3.y += f.y;
                f = __half22float2(v4); a0.x += f.x; a0.y += f.y;
                f = __half22float2(v5); a1.x += f.x; a1.y += f.y;
                f = __half22float2(v6); a2.x += f.x; a2.y += f.y;
                f = __half22float2(v7); a3.x += f.x; a3.y += f.y;
            }
            for (; e + 3 < rem; e += 4) {
                int s0 = __shfl_sync(0xffffffffu, idx, e);
                int s1 = __shfl_sync(0xffffffffu, idx, e + 1);
                int s2 = __shfl_sync(0xffffffffu, idx, e + 2);
                int s3 = __shfl_sync(0xffffffffu, idx, e + 3);
                __half2 v0 = rows[(size_t)s0 * 32 + lane];
                __half2 v1 = rows[(size_t)s1 * 32 + lane];
                __half2 v2 = rows[(size_t)s2 * 32 + lane];
                __half2 v3 = rows[(size_t)s3 * 32 + lane];
                float2 f;
                f = __half22float2(v0); a0.x += f.x; a0.y += f.y;
                f = __half22float2(v1); a1.x += f.x; a1.y += f.y;
                f = __half22float2(v2); a2.x += f.x; a2.y += f.y;
                f = __half22float2(v3); a3.x += f.x; a3.y += f.y;
            }
            for (; e < rem; e++) {
                int s = __shfl_sync(0xffffffffu, idx, e);
                float2 f = __half22float2(rows[(size_t)s * 32 + lane]);
                a0.x += f.x; a0.y += f.y;
            }
        }
        float di = g_dinv[i];
        float h0 = fmaf(a0.x + a1.x + a2.x + a3.x, di, bj.x);
        float h1 = fmaf(a0.y + a1.y + a2.y + a3.y, di, bj.y);
        if (relu) { h0 = fmaxf(h0, 0.f); h1 = fmaxf(h1, 0.f); }
        act[(2 * lane) * ASTR + n]     = h0;
        act[(2 * lane + 1) * ASTR + n] = h1;
    }
}

// ---------------------------------------------------------------------
// conv1: gather(hA)+relu -> @Wc2 -> scale by dinv -> hB (fp16 rows)
__global__ void __launch_bounds__(256) k_conv1(const float* __restrict__ bc1,
                                               const float* __restrict__ Wc2) {
    __shared__ __align__(16) float act[64 * ASTR];
    const int t  = threadIdx.x;
    const int i0 = blockIdx.x * TILE;

    gather_tile(g_hA, bc1, true, i0, act);
    __syncthreads();

    const int jt = t & 15, ng = t >> 4;
    const int j4 = jt * 4, n4 = ng * 4;

    ull c01[4], c23[4];
    #pragma unroll
    for (int a = 0; a < 4; a++) { c01[a] = 0ULL; c23[a] = 0ULL; }

    #pragma unroll 4
    for (int k = 0; k < 64; k++) {
        ulonglong2 w = __ldg((const ulonglong2*)&Wc2[k * 64 + j4]);
        float4 av = *(const float4*)&act[k * ASTR + n4];
        ull a0, a1, a2, a3;
        DUP2(a0, av.x); DUP2(a1, av.y); DUP2(a2, av.z); DUP2(a3, av.w);
        FFMA2(c01[0], w.x, a0); FFMA2(c23[0], w.y, a0);
        FFMA2(c01[1], w.x, a1); FFMA2(c23[1], w.y, a1);
        FFMA2(c01[2], w.x, a2); FFMA2(c23[2], w.y, a2);
        FFMA2(c01[3], w.x, a3); FFMA2(c23[3], w.y, a3);
    }

    #pragma unroll
    for (int nn = 0; nn < 4; nn++) {
        float d = g_dinv[i0 + n4 + nn];
        float v0, v1, v2, v3;
        unpack2(v0, v1, c01[nn]);
        unpack2(v2, v3, c23[nn]);
        g_hB[(size_t)(i0 + n4 + nn) * 32 + jt * 2]     = __floats2half2_rn(v0 * d, v1 * d);
        g_hB[(size_t)(i0 + n4 + nn) * 32 + jt * 2 + 1] = __floats2half2_rn(v2 * d, v3 * d);
    }
}

// ---------------------------------------------------------------------
// conv2: gather(hB) -> recovery MLP (64->128->64->1) + residual.
__global__ void __launch_bounds__(256) k_conv2(
        const float* __restrict__ x,
        const float* __restrict__ bc2,
        const float* __restrict__ Wr1, const float* __restrict__ br1,
        const float* __restrict__ Wr2, const float* __restrict__ br2,
        const float* __restrict__ Wr3, const float* __restrict__ br3,
        float* __restrict__ out) {
    __shared__ __align__(16) float sm[128 * ASTR];   // hbuf rows 0..63, then r1
    __shared__ float red[TILE];

    const int t  = threadIdx.x;
    const int i0 = blockIdx.x * TILE;

    gather_tile(g_hB, bc2, false, i0, sm);
    __syncthreads();

    const int jt = t & 15, ng = t >> 4;
    const int j4 = jt * 4, n4 = ng * 4;

    // r1 = relu(h @ Wr1 + br1): j-halves jA = j4, jB = 64 + j4; 4n each
    {
        ull cA01[4], cA23[4], cB01[4], cB23[4];
        #pragma unroll
        for (int a = 0; a < 4; a++) { cA01[a]=0ULL; cA23[a]=0ULL; cB01[a]=0ULL; cB23[a]=0ULL; }

        #pragma unroll 2
        for (int k = 0; k < 64; k++) {
            ulonglong2 wa = __ldg((const ulonglong2*)&Wr1[k * 128 + j4]);
            ulonglong2 wb = __ldg((const ulonglong2*)&Wr1[k * 128 + 64 + j4]);
            float4 av = *(const float4*)&sm[k * ASTR + n4];
            ull a0, a1, a2, a3;
            DUP2(a0, av.x); DUP2(a1, av.y); DUP2(a2, av.z); DUP2(a3, av.w);
            FFMA2(cA01[0], wa.x, a0); FFMA2(cA23[0], wa.y, a0);
            FFMA2(cA01[1], wa.x, a1); FFMA2(cA23[1], wa.y, a1);
            FFMA2(cA01[2], wa.x, a2); FFMA2(cA23[2], wa.y, a2);
            FFMA2(cA01[3], wa.x, a3); FFMA2(cA23[3], wa.y, a3);
            FFMA2(cB01[0], wb.x, a0); FFMA2(cB23[0], wb.y, a0);
            FFMA2(cB01[1], wb.x, a1); FFMA2(cB23[1], wb.y, a1);
            FFMA2(cB01[2], wb.x, a2); FFMA2(cB23[2], wb.y, a2);
            FFMA2(cB01[3], wb.x, a3); FFMA2(cB23[3], wb.y, a3);
        }
        __syncthreads();   // hbuf dead; safe to overwrite sm with r1

        float lo0[4], hi0[4], lo2[4], hi2[4];
        float Bl0[4], Bh0[4], Bl2[4], Bh2[4];
        #pragma unroll
        for (int nn = 0; nn < 4; nn++) {
            unpack2(lo0[nn], hi0[nn], cA01[nn]);
            unpack2(lo2[nn], hi2[nn], cA23[nn]);
            unpack2(Bl0[nn], Bh0[nn], cB01[nn]);
            unpack2(Bl2[nn], Bh2[nn], cB23[nn]);
        }
        float b0 = __ldg(&br1[j4]),      b1 = __ldg(&br1[j4 + 1]);
        float b2 = __ldg(&br1[j4 + 2]),  b3 = __ldg(&br1[j4 + 3]);
        float c0 = __ldg(&br1[64 + j4]),     c1 = __ldg(&br1[64 + j4 + 1]);
        float c2 = __ldg(&br1[64 + j4 + 2]), c3 = __ldg(&br1[64 + j4 + 3]);
        *(float4*)&sm[(j4 + 0) * ASTR + n4] = make_float4(
            fmaxf(lo0[0]+b0,0.f), fmaxf(lo0[1]+b0,0.f), fmaxf(lo0[2]+b0,0.f), fmaxf(lo0[3]+b0,0.f));
        *(float4*)&sm[(j4 + 1) * ASTR + n4] = make_float4(
            fmaxf(hi0[0]+b1,0.f), fmaxf(hi0[1]+b1,0.f), fmaxf(hi0[2]+b1,0.f), fmaxf(hi0[3]+b1,0.f));
        *(float4*)&sm[(j4 + 2) * ASTR + n4] = make_float4(
            fmaxf(lo2[0]+b2,0.f), fmaxf(lo2[1]+b2,0.f), fmaxf(lo2[2]+b2,0.f), fmaxf(lo2[3]+b2,0.f));
        *(float4*)&sm[(j4 + 3) * ASTR + n4] = make_float4(
            fmaxf(hi2[0]+b3,0.f), fmaxf(hi2[1]+b3,0.f), fmaxf(hi2[2]+b3,0.f), fmaxf(hi2[3]+b3,0.f));
        *(float4*)&sm[(64 + j4 + 0) * ASTR + n4] = make_float4(
            fmaxf(Bl0[0]+c0,0.f), fmaxf(Bl0[1]+c0,0.f), fmaxf(Bl0[2]+c0,0.f), fmaxf(Bl0[3]+c0,0.f));
        *(float4*)&sm[(64 + j4 + 1) * ASTR + n4] = make_float4(
            fmaxf(Bh0[0]+c1,0.f), fmaxf(Bh0[1]+c1,0.f), fmaxf(Bh0[2]+c1,0.f), fmaxf(Bh0[3]+c1,0.f));
        *(float4*)&sm[(64 + j4 + 2) * ASTR + n4] = make_float4(
            fmaxf(Bl2[0]+c2,0.f), fmaxf(Bl2[1]+c2,0.f), fmaxf(Bl2[2]+c2,0.f), fmaxf(Bl2[3]+c2,0.f));
        *(float4*)&sm[(64 + j4 + 3) * ASTR + n4] = make_float4(
            fmaxf(Bh2[0]+c3,0.f), fmaxf(Bh2[1]+c3,0.f), fmaxf(Bh2[2]+c3,0.f), fmaxf(Bh2[3]+c3,0.f));
    }
    __syncthreads();

    // r2 = relu(r1 @ Wr2 + br2), then dot Wr3 and reduce over jt
    {
        ull c01[4], c23[4];
        #pragma unroll
        for (int a = 0; a < 4; a++) { c01[a] = 0ULL; c23[a] = 0ULL; }

        #pragma unroll 4
        for (int k = 0; k < 128; k++) {
            ulonglong2 w = __ldg((const ulonglong2*)&Wr2[k * 64 + j4]);
            float4 av = *(const float4*)&sm[k * ASTR + n4];
            ull a0, a1, a2, a3;
            DUP2(a0, av.x); DUP2(a1, av.y); DUP2(a2, av.z); DUP2(a3, av.w);
            FFMA2(c01[0], w.x, a0); FFMA2(c23[0], w.y, a0);
            FFMA2(c01[1], w.x, a1); FFMA2(c23[1], w.y, a1);
            FFMA2(c01[2], w.x, a2); FFMA2(c23[2], w.y, a2);
            FFMA2(c01[3], w.x, a3); FFMA2(c23[3], w.y, a3);
        }

        float b0 = __ldg(&br2[j4]),     b1 = __ldg(&br2[j4 + 1]);
        float b2 = __ldg(&br2[j4 + 2]), b3 = __ldg(&br2[j4 + 3]);
        float w0 = __ldg(&Wr3[j4]),     w1 = __ldg(&Wr3[j4 + 1]);
        float w2 = __ldg(&Wr3[j4 + 2]), w3 = __ldg(&Wr3[j4 + 3]);

        float p[4];
        #pragma unroll
        for (int nn = 0; nn < 4; nn++) {
            float v0, v1, v2, v3;
            unpack2(v0, v1, c01[nn]);
            unpack2(v2, v3, c23[nn]);
            float s = fmaxf(v0 + b0, 0.f) * w0;
            s = fmaf(fmaxf(v1 + b1, 0.f), w1, s);
            s = fmaf(fmaxf(v2 + b2, 0.f), w2, s);
            s = fmaf(fmaxf(v3 + b3, 0.f), w3, s);
            p[nn] = s;
        }
        #pragma unroll
        for (int o = 1; o <= 8; o <<= 1) {
            #pragma unroll
            for (int nn = 0; nn < 4; nn++)
                p[nn] += __shfl_xor_sync(0xffffffffu, p[nn], o);
        }
        if (jt == 0) {
            red[n4]     = p[0];
            red[n4 + 1] = p[1];
            red[n4 + 2] = p[2];
            red[n4 + 3] = p[3];
        }
    }
    __syncthreads();

    if (t < TILE)
        out[i0 + t] = red[t] + __ldg(&br3[0]) + x[2 * (i0 + t)];
}

// ---------------------------------------------------------------------
extern "C" void kernel_launch(void* const* d_in, const int* in_sizes, int n_in,
                              void* d_out, int out_size) {
    const float* x    = (const float*)d_in[0];
    const int*   ei32 = (const int*)d_in[1];
    const float* Wp  = (const float*)d_in[2];
    const float* bp  = (const float*)d_in[3];
    const float* Wg  = (const float*)d_in[4];
    const float* bg  = (const float*)d_in[5];
    const float* Emb = (const float*)d_in[6];
    const float* Wet = (const float*)d_in[7];
    const float* bet = (const float*)d_in[8];
    const float* Wpb = (const float*)d_in[9];
    const float* bpb = (const float*)d_in[10];
    const float* Wc1 = (const float*)d_in[11];
    const float* bc1 = (const float*)d_in[12];
    const float* Wc2 = (const float*)d_in[13];
    const float* bc2 = (const float*)d_in[14];
    const float* Wr1 = (const float*)d_in[15];
    const float* br1 = (const float*)d_in[16];
    const float* Wr2 = (const float*)d_in[17];
    const float* br2 = (const float*)d_in[18];
    const float* Wr3 = (const float*)d_in[19];
    const float* br3 = (const float*)d_in[20];
    float* out = (float*)d_out;

    const int n = in_sizes[0] / 2;   // 160000
    const int E = in_sizes[1] / 2;   // 3200000
    const int nblocks = n / TILE;    // 2500

    k_pre1a      <<<64, 64>>>(Wpb, Wc1);              // #0  (resets g_flag)
    k_pre1b      <<<65, 64>>>(Wp, bp, Wg, bg, Wet, bet, Wpb, bpb, Wc1);  // #1
    k_zero_detect<<<(n + 255) / 256, 256>>>(ei32, E, n);                  // #2

    // #3 — DIAGNOSTIC duplicate of conv2 (the launch slot ncu captures).
    // Reads prior-replay CSR/hB state (valid & representative in steady-state
    // replays).  Writes only `out`, fully overwritten by the real conv2 below,
    // so the final output is unchanged.  Removed next round.
    k_conv2<<<nblocks, 256>>>(x, bc2, Wr1, br1, Wr2, br2, Wr3, br3, out);

    k_deg        <<<(E + 255) / 256, 256>>>(ei32, E);
    k_dinv       <<<(n + 255) / 256, 256>>>(n);
    k_scan       <<<1, 1024>>>();
    k_fill       <<<(E + 255) / 256, 256>>>(ei32, E);
    k_pre2       <<<(NGENES + 3) / 4, 256>>>(Emb);

    k_node <<<n / 8, 256>>>(x);
    k_conv1<<<nblocks, 256>>>(bc1, Wc2);
    k_conv2<<<nblocks, 256>>>(x, bc2, Wr1, br1, Wr2, br2, Wr3, br3, out);
}

// round 16
// speedup vs baseline: 1.4298x; 1.4298x over previous
#include <cuda_runtime.h>
#include <cuda_fp16.h>

#define NN      160000
#define HH      64
#define EE      3200000
#define NGENES  5000
#define TILE    64
#define ASTR    68          // act row stride in floats (16B-aligned rows)

typedef unsigned long long ull;

// -------- scratch (static device globals; no runtime allocation) --------
__device__ int     g_flag;
__device__ int     g_cnt[NN];
__device__ int     g_cur[NN];
__device__ int     g_off[NN + 1];
__device__ int     g_srcl[EE];
__device__ float   g_dinv[NN];
__device__ __half2 g_hA[NN * 32];    // scaled h0@Wc1 (fp16 rows, 128B each)
__device__ __half2 g_hB[NN * 32];    // scaled h1@Wc2 (fp16 rows)
// precompute scratch
__device__ float g_Wtc[64 * 64];     // WpbT @ Wc1
__device__ float g_Wtot[64 * 64];    // WetB @ Wtc
__device__ float g_E3[NGENES * 64];  // renorm(Emb) @ Wtot
__device__ float g_P[64], g_Q[64], g_R[64];

// ---------------- f32x2 packed-FMA helpers (lower to HW FFMA2) ----------
#define FFMA2(c, a, b) asm("fma.rn.f32x2 %0, %1, %2, %0;" : "+l"(c) : "l"(a), "l"(b))
#define DUP2(d, s) asm("mov.b64 %0, {%1, %2};" : "=l"(d) \
                       : "r"(__float_as_uint(s)), "r"(__float_as_uint(s)))
__device__ __forceinline__ void unpack2(float& lo, float& hi, ull s) {
    unsigned int ulo, uhi;
    asm("mov.b64 {%0, %1}, %2;" : "=r"(ulo), "=r"(uhi) : "l"(s));
    lo = __uint_as_float(ulo); hi = __uint_as_float(uhi);
}

// ---------------------------------------------------------------------
__global__ void k_zero_detect(const int* __restrict__ ei32, int E, int n) {
    int t = blockIdx.x * blockDim.x + threadIdx.x;
    if (t < n) { g_cnt[t] = 0; g_cur[t] = 0; }
    if (t < 16384) {
        int acc = 0;
        const long long total = 2LL * E;
        const long long stride = total / 65536;
        #pragma unroll
        for (int q = 0; q < 4; q++) {
            long long widx = ((long long)(t * 4 + q) * stride) | 1LL;
            if (widx < total) acc |= ei32[widx];
        }
        #pragma unroll
        for (int o = 16; o; o >>= 1) acc |= __shfl_xor_sync(0xffffffffu, acc, o);
        if ((threadIdx.x & 31) == 0 && acc) atomicOr(&g_flag, 1);
    }
}

__device__ __forceinline__ int ld_src(const int* __restrict__ ei32, int E, int e, bool is64) {
    int v = is64 ? ei32[2 * e] : ei32[e];
    return min(max(v, 0), NN - 1);
}
__device__ __forceinline__ int ld_dst(const int* __restrict__ ei32, int E, int e, bool is64) {
    int v = is64 ? ei32[2 * (E + e)] : ei32[E + e];
    return min(max(v, 0), NN - 1);
}

__global__ void k_deg(const int* __restrict__ ei32, int E) {
    int e = blockIdx.x * blockDim.x + threadIdx.x;
    bool is64 = (g_flag == 0);
    if (e < E) atomicAdd(&g_cnt[ld_dst(ei32, E, e, is64)], 1);
}

__global__ void k_dinv(int n) {
    int i = blockIdx.x * blockDim.x + threadIdx.x;
    if (i < n) g_dinv[i] = rsqrtf(1.0f + (float)g_cnt[i]);
}

__global__ void k_scan() {
    __shared__ int ssum[1024];
    const int T = 1024;
    const int per = (NN + T - 1) / T;
    int tid = threadIdx.x;
    int a = tid * per;
    int b = a + per; if (b > NN) b = NN;
    int s = 0;
    for (int i = a; i < b; i++) s += g_cnt[i];
    ssum[tid] = s;
    __syncthreads();
    for (int o = 1; o < T; o <<= 1) {
        int v = (tid >= o) ? ssum[tid - o] : 0;
        __syncthreads();
        ssum[tid] += v;
        __syncthreads();
    }
    int run = (tid == 0) ? 0 : ssum[tid - 1];
    for (int i = a; i < b; i++) { g_off[i] = run; run += g_cnt[i]; }
    if (tid == T - 1) g_off[NN] = run;
}

__global__ void k_fill(const int* __restrict__ ei32, int E) {
    int e = blockIdx.x * blockDim.x + threadIdx.x;
    bool is64 = (g_flag == 0);
    if (e < E) {
        int s = ld_src(ei32, E, e, is64);
        int d = ld_dst(ei32, E, e, is64);
        g_srcl[g_off[d] + atomicAdd(&g_cur[d], 1)] = s;
    }
}

// ---------------------------------------------------------------------
__global__ void k_pre1a(const float* __restrict__ Wpb, const float* __restrict__ Wc1) {
    const int r = blockIdx.x, j = threadIdx.x;
    if (r == 0 && j == 0) g_flag = 0;
    float s = 0.f;
    #pragma unroll 4
    for (int k = 0; k < 64; k++) s = fmaf(__ldg(&Wpb[r * 64 + k]), __ldg(&Wc1[k * 64 + j]), s);
    g_Wtc[r * 64 + j] = s;
}

__global__ void k_pre1b(const float* __restrict__ Wp, const float* __restrict__ bp,
                        const float* __restrict__ Wg, const float* __restrict__ bg,
                        const float* __restrict__ Wet, const float* __restrict__ bet,
                        const float* __restrict__ Wpb, const float* __restrict__ bpb,
                        const float* __restrict__ Wc1) {
    const int j = threadIdx.x;
    if (blockIdx.x < 64) {
        const int r = blockIdx.x;
        float s = 0.f;
        #pragma unroll 4
        for (int k = 0; k < 64; k++) s = fmaf(__ldg(&Wet[(64 + r) * 64 + k]), g_Wtc[k * 64 + j], s);
        g_Wtot[r * 64 + j] = s;
        return;
    }
    __shared__ float sv[64];
    float u = 0.f;
    for (int k = 0; k < 64; k++) u = fmaf(Wg[k], Wet[k * 64 + j], u);
    sv[j] = u;
    __syncthreads();
    float p = 0.f;
    for (int k = 0; k < 64; k++) p = fmaf(sv[k], g_Wtc[k * 64 + j], p);
    g_P[j] = p;
    __syncthreads();
    float v = 0.f;
    for (int k = 0; k < 64; k++) v = fmaf(Wp[k], Wpb[(64 + k) * 64 + j], v);
    sv[j] = v;
    __syncthreads();
    float qq = 0.f;
    for (int k = 0; k < 64; k++) qq = fmaf(sv[k], Wc1[k * 64 + j], qq);
    g_Q[j] = qq;
    __syncthreads();
    float r1 = bet[j];
    for (int k = 0; k < 64; k++) r1 = fmaf(bg[k], Wet[k * 64 + j], r1);
    sv[j] = r1;
    __syncthreads();
    float r2 = bpb[j];
    for (int k = 0; k < 64; k++) r2 = fmaf(sv[k], Wpb[k * 64 + j], r2);
    for (int k = 0; k < 64; k++) r2 = fmaf(bp[k], Wpb[(64 + k) * 64 + j], r2);
    __syncthreads();
    sv[j] = r2;
    __syncthreads();
    float rr = 0.f;
    for (int k = 0; k < 64; k++) rr = fmaf(sv[k], Wc1[k * 64 + j], rr);
    g_R[j] = rr;
}

__global__ void __launch_bounds__(256) k_pre2(const float* __restrict__ Emb) {
    __shared__ float se[4][64];
    __shared__ float ssc[4];
    __shared__ float sp[4][2];
    const int t = threadIdx.x;
    const int gl = t >> 6, j = t & 63;
    const int g = blockIdx.x * 4 + gl;
    if (g >= NGENES) return;

    float e = Emb[g * 64 + j];
    se[gl][j] = e;
    float ss = e * e;
    #pragma unroll
    for (int o = 16; o; o >>= 1) ss += __shfl_xor_sync(0xffffffffu, ss, o);
    if ((j & 31) == 0) sp[gl][j >> 5] = ss;
    __syncthreads();
    if (j == 0) {
        float nrm = sqrtf(sp[gl][0] + sp[gl][1]);
        ssc[gl] = fminf(1.0f, 1.0f / fmaxf(nrm, 1e-12f));
    }
    __syncthreads();

    float acc = 0.f;
    #pragma unroll 4
    for (int k = 0; k < 64; k++) acc = fmaf(se[gl][k], g_Wtot[k * 64 + j], acc);
    g_E3[g * 64 + j] = acc * ssc[gl];
}

// node: hA[i] = (E3[gid] + basal*P + pert*Q + R) * dinv[i]  (fp16 rows)
__global__ void __launch_bounds__(256) k_node(const float* __restrict__ x) {
    const int lane = threadIdx.x & 31;
    const int i = blockIdx.x * 8 + (threadIdx.x >> 5);
    const float basal = __ldg(&x[2 * i]);
    const float pert  = __ldg(&x[2 * i + 1]);
    const int gid = i % NGENES;
    const float di = g_dinv[i];
    float2 e3 = ((const float2*)(g_E3 + gid * 64))[lane];
    float2 P  = ((const float2*)g_P)[lane];
    float2 Q  = ((const float2*)g_Q)[lane];
    float2 R  = ((const float2*)g_R)[lane];
    float w0 = (e3.x + basal * P.x + pert * Q.x + R.x) * di;
    float w1 = (e3.y + basal * P.y + pert * Q.y + R.y) * di;
    g_hA[(size_t)i * 32 + lane] = __floats2half2_rn(w0, w1);
}

// ---------------------------------------------------------------------
// gather: warp-per-node, 8 nodes serially per warp (TILE=64).  fp16 rows:
// lane l loads half2 (cols 2l,2l+1) -> one 128B line per edge-row.
// Accumulate in fp32; 8-deep load batches (MLP 8, proven shape).
__device__ __forceinline__ void gather_tile(const __half2* __restrict__ rows,
                                            const float* __restrict__ bias,
                                            bool relu, int i0,
                                            float* __restrict__ act) {
    const int lane = threadIdx.x & 31;
    const int w    = threadIdx.x >> 5;       // 0..7
    const float2 bj = *(const float2*)&bias[2 * lane];

    for (int r = 0; r < 8; r++) {
        const int n = w * 8 + r;
        const int i = i0 + n;
        const int o0 = g_off[i];
        const int D  = g_off[i + 1] - o0;

        float2 a0 = __half22float2(rows[(size_t)i * 32 + lane]);  // own row
        float2 a1 = make_float2(0.f, 0.f);
        float2 a2 = make_float2(0.f, 0.f);
        float2 a3 = make_float2(0.f, 0.f);

        int base = o0;
        const int nfull = D >> 5;
        for (int c = 0; c < nfull; c++) {
            int idx = g_srcl[base + lane];
            base += 32;
            #pragma unroll
            for (int h = 0; h < 4; h++) {
                int s0 = __shfl_sync(0xffffffffu, idx, h * 8 + 0);
                int s1 = __shfl_sync(0xffffffffu, idx, h * 8 + 1);
                int s2 = __shfl_sync(0xffffffffu, idx, h * 8 + 2);
                int s3 = __shfl_sync(0xffffffffu, idx, h * 8 + 3);
                int s4 = __shfl_sync(0xffffffffu, idx, h * 8 + 4);
                int s5 = __shfl_sync(0xffffffffu, idx, h * 8 + 5);
                int s6 = __shfl_sync(0xffffffffu, idx, h * 8 + 6);
                int s7 = __shfl_sync(0xffffffffu, idx, h * 8 + 7);
                __half2 v0 = rows[(size_t)s0 * 32 + lane];
                __half2 v1 = rows[(size_t)s1 * 32 + lane];
                __half2 v2 = rows[(size_t)s2 * 32 + lane];
                __half2 v3 = rows[(size_t)s3 * 32 + lane];
                __half2 v4 = rows[(size_t)s4 * 32 + lane];
                __half2 v5 = rows[(size_t)s5 * 32 + lane];
                __half2 v6 = rows[(size_t)s6 * 32 + lane];
                __half2 v7 = rows[(size_t)s7 * 32 + lane];
                float2 f;
                f = __half22float2(v0); a0.x += f.x; a0.y += f.y;
                f = __half22float2(v1); a1.x += f.x; a1.y += f.y;
                f = __half22float2(v2); a2.x += f.x; a2.y += f.y;
                f = __half22float2(v3); a3.x += f.x; a3.y += f.y;
                f = __half22float2(v4); a0.x += f.x; a0.y += f.y;
                f = __half22float2(v5); a1.x += f.x; a1.y += f.y;
                f = __half22float2(v6); a2.x += f.x; a2.y += f.y;
                f = __half22float2(v7); a3.x += f.x; a3.y += f.y;
            }
        }
        const int rem = D & 31;
        if (rem) {
            int idx = (lane < rem) ? g_srcl[base + lane] : 0;
            int e = 0;
            for (; e + 7 < rem; e += 8) {
                int s0 = __shfl_sync(0xffffffffu, idx, e);
                int s1 = __shfl_sync(0xffffffffu, idx, e + 1);
                int s2 = __shfl_sync(0xffffffffu, idx, e + 2);
                int s3 = __shfl_sync(0xffffffffu, idx, e + 3);
                int s4 = __shfl_sync(0xffffffffu, idx, e + 4);
                int s5 = __shfl_sync(0xffffffffu, idx, e + 5);
                int s6 = __shfl_sync(0xffffffffu, idx, e + 6);
                int s7 = __shfl_sync(0xffffffffu, idx, e + 7);
                __half2 v0 = rows[(size_t)s0 * 32 + lane];
                __half2 v1 = rows[(size_t)s1 * 32 + lane];
                __half2 v2 = rows[(size_t)s2 * 32 + lane];
                __half2 v3 = rows[(size_t)s3 * 32 + lane];
                __half2 v4 = rows[(size_t)s4 * 32 + lane];
                __half2 v5 = rows[(size_t)s5 * 32 + lane];
                __half2 v6 = rows[(size_t)s6 * 32 + lane];
                __half2 v7 = rows[(size_t)s7 * 32 + lane];
                float2 f;
                f = __half22float2(v0); a0.x += f.x; a0.y += f.y;
                f = __half22float2(v1); a1.x += f.x; a1.y += f.y;
                f = __half22float2(v2); a2.x += f.x; a2.y += f.y;
                f = __half22float2(v3); a3.x += f.x; a3.y += f.y;
                f = __half22float2(v4); a0.x += f.x; a0.y += f.y;
                f = __half22float2(v5); a1.x += f.x; a1.y += f.y;
                f = __half22float2(v6); a2.x += f.x; a2.y += f.y;
                f = __half22float2(v7); a3.x += f.x; a3.y += f.y;
            }
            for (; e + 3 < rem; e += 4) {
                int s0 = __shfl_sync(0xffffffffu, idx, e);
                int s1 = __shfl_sync(0xffffffffu, idx, e + 1);
                int s2 = __shfl_sync(0xffffffffu, idx, e + 2);
                int s3 = __shfl_sync(0xffffffffu, idx, e + 3);
                __half2 v0 = rows[(size_t)s0 * 32 + lane];
                __half2 v1 = rows[(size_t)s1 * 32 + lane];
                __half2 v2 = rows[(size_t)s2 * 32 + lane];
                __half2 v3 = rows[(size_t)s3 * 32 + lane];
                float2 f;
                f = __half22float2(v0); a0.x += f.x; a0.y += f.y;
                f = __half22float2(v1); a1.x += f.x; a1.y += f.y;
                f = __half22float2(v2); a2.x += f.x; a2.y += f.y;
                f = __half22float2(v3); a3.x += f.x; a3.y += f.y;
            }
            for (; e < rem; e++) {
                int s = __shfl_sync(0xffffffffu, idx, e);
                float2 f = __half22float2(rows[(size_t)s * 32 + lane]);
                a0.x += f.x; a0.y += f.y;
            }
        }
        float di = g_dinv[i];
        float h0 = fmaf(a0.x + a1.x + a2.x + a3.x, di, bj.x);
        float h1 = fmaf(a0.y + a1.y + a2.y + a3.y, di, bj.y);
        if (relu) { h0 = fmaxf(h0, 0.f); h1 = fmaxf(h1, 0.f); }
        act[(2 * lane) * ASTR + n]     = h0;
        act[(2 * lane + 1) * ASTR + n] = h1;
    }
}

// ---------------------------------------------------------------------
// conv1: gather(hA)+relu -> @Wc2 -> scale by dinv -> hB (fp16 rows)
__global__ void __launch_bounds__(256, 5) k_conv1(const float* __restrict__ bc1,
                                                  const float* __restrict__ Wc2) {
    __shared__ __align__(16) float act[64 * ASTR];
    const int t  = threadIdx.x;
    const int i0 = blockIdx.x * TILE;

    gather_tile(g_hA, bc1, true, i0, act);
    __syncthreads();

    const int jt = t & 15, ng = t >> 4;
    const int j4 = jt * 4, n4 = ng * 4;

    ull c01[4], c23[4];
    #pragma unroll
    for (int a = 0; a < 4; a++) { c01[a] = 0ULL; c23[a] = 0ULL; }

    #pragma unroll 4
    for (int k = 0; k < 64; k++) {
        ulonglong2 w = __ldg((const ulonglong2*)&Wc2[k * 64 + j4]);
        float4 av = *(const float4*)&act[k * ASTR + n4];
        ull a0, a1, a2, a3;
        DUP2(a0, av.x); DUP2(a1, av.y); DUP2(a2, av.z); DUP2(a3, av.w);
        FFMA2(c01[0], w.x, a0); FFMA2(c23[0], w.y, a0);
        FFMA2(c01[1], w.x, a1); FFMA2(c23[1], w.y, a1);
        FFMA2(c01[2], w.x, a2); FFMA2(c23[2], w.y, a2);
        FFMA2(c01[3], w.x, a3); FFMA2(c23[3], w.y, a3);
    }

    #pragma unroll
    for (int nn = 0; nn < 4; nn++) {
        float d = g_dinv[i0 + n4 + nn];
        float v0, v1, v2, v3;
        unpack2(v0, v1, c01[nn]);
        unpack2(v2, v3, c23[nn]);
        g_hB[(size_t)(i0 + n4 + nn) * 32 + jt * 2]     = __floats2half2_rn(v0 * d, v1 * d);
        g_hB[(size_t)(i0 + n4 + nn) * 32 + jt * 2 + 1] = __floats2half2_rn(v2 * d, v3 * d);
    }
}

// ---------------------------------------------------------------------
// conv2: gather(hB) -> recovery MLP (64->128->64->1) + residual.
// r1 computed in TWO j-half passes (8 ull accumulators live at a time,
// halving register pressure vs the single-pass version):
//   pass 1: j-half 64+j4, reads hbuf (sm rows 0..63), writes sm rows 64..127
//           (disjoint from hbuf -> no sync needed before the writes)
//   pass 2: j-half j4, reads hbuf, THEN syncs, writes sm rows 0..63
__global__ void __launch_bounds__(256, 5) k_conv2(
        const float* __restrict__ x,
        const float* __restrict__ bc2,
        const float* __restrict__ Wr1, const float* __restrict__ br1,
        const float* __restrict__ Wr2, const float* __restrict__ br2,
        const float* __restrict__ Wr3, const float* __restrict__ br3,
        float* __restrict__ out) {
    __shared__ __align__(16) float sm[128 * ASTR];   // hbuf rows 0..63, then r1
    __shared__ float red[TILE];

    const int t  = threadIdx.x;
    const int i0 = blockIdx.x * TILE;

    gather_tile(g_hB, bc2, false, i0, sm);
    __syncthreads();

    const int jt = t & 15, ng = t >> 4;
    const int j4 = jt * 4, n4 = ng * 4;

    // ---- r1 pass 1: output rows 64+j4 .. 64+j4+3 ----
    {
        ull c01[4], c23[4];
        #pragma unroll
        for (int a = 0; a < 4; a++) { c01[a] = 0ULL; c23[a] = 0ULL; }
        #pragma unroll 4
        for (int k = 0; k < 64; k++) {
            ulonglong2 w = __ldg((const ulonglong2*)&Wr1[k * 128 + 64 + j4]);
            float4 av = *(const float4*)&sm[k * ASTR + n4];
            ull a0, a1, a2, a3;
            DUP2(a0, av.x); DUP2(a1, av.y); DUP2(a2, av.z); DUP2(a3, av.w);
            FFMA2(c01[0], w.x, a0); FFMA2(c23[0], w.y, a0);
            FFMA2(c01[1], w.x, a1); FFMA2(c23[1], w.y, a1);
            FFMA2(c01[2], w.x, a2); FFMA2(c23[2], w.y, a2);
            FFMA2(c01[3], w.x, a3); FFMA2(c23[3], w.y, a3);
        }
        // rows 64..127 are not hbuf -> safe to write without a sync
        float lo0[4], hi0[4], lo2[4], hi2[4];
        #pragma unroll
        for (int nn = 0; nn < 4; nn++) {
            unpack2(lo0[nn], hi0[nn], c01[nn]);
            unpack2(lo2[nn], hi2[nn], c23[nn]);
        }
        float b0 = __ldg(&br1[64 + j4]),     b1 = __ldg(&br1[64 + j4 + 1]);
        float b2 = __ldg(&br1[64 + j4 + 2]), b3 = __ldg(&br1[64 + j4 + 3]);
        *(float4*)&sm[(64 + j4 + 0) * ASTR + n4] = make_float4(
            fmaxf(lo0[0]+b0,0.f), fmaxf(lo0[1]+b0,0.f), fmaxf(lo0[2]+b0,0.f), fmaxf(lo0[3]+b0,0.f));
        *(float4*)&sm[(64 + j4 + 1) * ASTR + n4] = make_float4(
            fmaxf(hi0[0]+b1,0.f), fmaxf(hi0[1]+b1,0.f), fmaxf(hi0[2]+b1,0.f), fmaxf(hi0[3]+b1,0.f));
        *(float4*)&sm[(64 + j4 + 2) * ASTR + n4] = make_float4(
            fmaxf(lo2[0]+b2,0.f), fmaxf(lo2[1]+b2,0.f), fmaxf(lo2[2]+b2,0.f), fmaxf(lo2[3]+b2,0.f));
        *(float4*)&sm[(64 + j4 + 3) * ASTR + n4] = make_float4(
            fmaxf(hi2[0]+b3,0.f), fmaxf(hi2[1]+b3,0.f), fmaxf(hi2[2]+b3,0.f), fmaxf(hi2[3]+b3,0.f));
    }

    // ---- r1 pass 2: output rows j4 .. j4+3 ----
    {
        ull c01[4], c23[4];
        #pragma unroll
        for (int a = 0; a < 4; a++) { c01[a] = 0ULL; c23[a] = 0ULL; }
        #pragma unroll 4
        for (int k = 0; k < 64; k++) {
            ulonglong2 w = __ldg((const ulonglong2*)&Wr1[k * 128 + j4]);
            float4 av = *(const float4*)&sm[k * ASTR + n4];
            ull a0, a1, a2, a3;
            DUP2(a0, av.x); DUP2(a1, av.y); DUP2(a2, av.z); DUP2(a3, av.w);
            FFMA2(c01[0], w.x, a0); FFMA2(c23[0], w.y, a0);
            FFMA2(c01[1], w.x, a1); FFMA2(c23[1], w.y, a1);
            FFMA2(c01[2], w.x, a2); FFMA2(c23[2], w.y, a2);
            FFMA2(c01[3], w.x, a3); FFMA2(c23[3], w.y, a3);
        }
        __syncthreads();   // all hbuf reads done; safe to overwrite rows 0..63
        float lo0[4], hi0[4], lo2[4], hi2[4];
        #pragma unroll
        for (int nn = 0; nn < 4; nn++) {
            unpack2(lo0[nn], hi0[nn], c01[nn]);
            unpack2(lo2[nn], hi2[nn], c23[nn]);
        }
        float b0 = __ldg(&br1[j4]),     b1 = __ldg(&br1[j4 + 1]);
        float b2 = __ldg(&br1[j4 + 2]), b3 = __ldg(&br1[j4 + 3]);
        *(float4*)&sm[(j4 + 0) * ASTR + n4] = make_float4(
            fmaxf(lo0[0]+b0,0.f), fmaxf(lo0[1]+b0,0.f), fmaxf(lo0[2]+b0,0.f), fmaxf(lo0[3]+b0,0.f));
        *(float4*)&sm[(j4 + 1) * ASTR + n4] = make_float4(
            fmaxf(hi0[0]+b1,0.f), fmaxf(hi0[1]+b1,0.f), fmaxf(hi0[2]+b1,0.f), fmaxf(hi0[3]+b1,0.f));
        *(float4*)&sm[(j4 + 2) * ASTR + n4] = make_float4(
            fmaxf(lo2[0]+b2,0.f), fmaxf(lo2[1]+b2,0.f), fmaxf(lo2[2]+b2,0.f), fmaxf(lo2[3]+b2,0.f));
        *(float4*)&sm[(j4 + 3) * ASTR + n4] = make_float4(
            fmaxf(hi2[0]+b3,0.f), fmaxf(hi2[1]+b3,0.f), fmaxf(hi2[2]+b3,0.f), fmaxf(hi2[3]+b3,0.f));
    }
    __syncthreads();

    // r2 = relu(r1 @ Wr2 + br2), then dot Wr3 and reduce over jt
    {
        ull c01[4], c23[4];
        #pragma unroll
        for (int a = 0; a < 4; a++) { c01[a] = 0ULL; c23[a] = 0ULL; }

        #pragma unroll 4
        for (int k = 0; k < 128; k++) {
            ulonglong2 w = __ldg((const ulonglong2*)&Wr2[k * 64 + j4]);
            float4 av = *(const float4*)&sm[k * ASTR + n4];
            ull a0, a1, a2, a3;
            DUP2(a0, av.x); DUP2(a1, av.y); DUP2(a2, av.z); DUP2(a3, av.w);
            FFMA2(c01[0], w.x, a0); FFMA2(c23[0], w.y, a0);
            FFMA2(c01[1], w.x, a1); FFMA2(c23[1], w.y, a1);
            FFMA2(c01[2], w.x, a2); FFMA2(c23[2], w.y, a2);
            FFMA2(c01[3], w.x, a3); FFMA2(c23[3], w.y, a3);
        }

        float b0 = __ldg(&br2[j4]),     b1 = __ldg(&br2[j4 + 1]);
        float b2 = __ldg(&br2[j4 + 2]), b3 = __ldg(&br2[j4 + 3]);
        float w0 = __ldg(&Wr3[j4]),     w1 = __ldg(&Wr3[j4 + 1]);
        float w2 = __ldg(&Wr3[j4 + 2]), w3 = __ldg(&Wr3[j4 + 3]);

        float p[4];
        #pragma unroll
        for (int nn = 0; nn < 4; nn++) {
            float v0, v1, v2, v3;
            unpack2(v0, v1, c01[nn]);
            unpack2(v2, v3, c23[nn]);
            float s = fmaxf(v0 + b0, 0.f) * w0;
            s = fmaf(fmaxf(v1 + b1, 0.f), w1, s);
            s = fmaf(fmaxf(v2 + b2, 0.f), w2, s);
            s = fmaf(fmaxf(v3 + b3, 0.f), w3, s);
            p[nn] = s;
        }
        #pragma unroll
        for (int o = 1; o <= 8; o <<= 1) {
            #pragma unroll
            for (int nn = 0; nn < 4; nn++)
                p[nn] += __shfl_xor_sync(0xffffffffu, p[nn], o);
        }
        if (jt == 0) {
            red[n4]     = p[0];
            red[n4 + 1] = p[1];
            red[n4 + 2] = p[2];
            red[n4 + 3] = p[3];
        }
    }
    __syncthreads();

    if (t < TILE)
        out[i0 + t] = red[t] + __ldg(&br3[0]) + x[2 * (i0 + t)];
}

// ---------------------------------------------------------------------
extern "C" void kernel_launch(void* const* d_in, const int* in_sizes, int n_in,
                              void* d_out, int out_size) {
    const float* x    = (const float*)d_in[0];
    const int*   ei32 = (const int*)d_in[1];
    const float* Wp  = (const float*)d_in[2];
    const float* bp  = (const float*)d_in[3];
    const float* Wg  = (const float*)d_in[4];
    const float* bg  = (const float*)d_in[5];
    const float* Emb = (const float*)d_in[6];
    const float* Wet = (const float*)d_in[7];
    const float* bet = (const float*)d_in[8];
    const float* Wpb = (const float*)d_in[9];
    const float* bpb = (const float*)d_in[10];
    const float* Wc1 = (const float*)d_in[11];
    const float* bc1 = (const float*)d_in[12];
    const float* Wc2 = (const float*)d_in[13];
    const float* bc2 = (const float*)d_in[14];
    const float* Wr1 = (const float*)d_in[15];
    const float* br1 = (const float*)d_in[16];
    const float* Wr2 = (const float*)d_in[17];
    const float* br2 = (const float*)d_in[18];
    const float* Wr3 = (const float*)d_in[19];
    const float* br3 = (const float*)d_in[20];
    float* out = (float*)d_out;

    const int n = in_sizes[0] / 2;   // 160000
    const int E = in_sizes[1] / 2;   // 3200000
    const int nblocks = n / TILE;    // 2500

    k_pre1a      <<<64, 64>>>(Wpb, Wc1);              // resets g_flag
    k_pre1b      <<<65, 64>>>(Wp, bp, Wg, bg, Wet, bet, Wpb, bpb, Wc1);
    k_zero_detect<<<(n + 255) / 256, 256>>>(ei32, E, n);
    k_deg        <<<(E + 255) / 256, 256>>>(ei32, E);
    k_dinv       <<<(n + 255) / 256, 256>>>(n);
    k_scan       <<<1, 1024>>>();
    k_fill       <<<(E + 255) / 256, 256>>>(ei32, E);
    k_pre2       <<<(NGENES + 3) / 4, 256>>>(Emb);

    k_node <<<n / 8, 256>>>(x);
    k_conv1<<<nblocks, 256>>>(bc1, Wc2);
    k_conv2<<<nblocks, 256>>>(x, bc2, Wr1, br1, Wr2, br2, Wr3, br3, out);
}